// round 1
// baseline (speedup 1.0000x reference)
#include <cuda_runtime.h>

#define BATCH 8
#define CIN   64
#define COUT  64
#define Hdim  64
#define Wdim  64
#define CTOT  69
#define HW    (Hdim*Wdim)
#define NPIX  (BATCH*HW)

// Scratch (static device globals — no allocation)
__device__ float g_conv[BATCH*COUT*HW];   // raw conv output (pre-BN)
__device__ float g_sq[NPIX];              // 1x1-conv "shape query"
__device__ float g_psum[COUT*32];         // per-(channel, block) partial sums
__device__ float g_psumsq[COUT*32];
__device__ float g_mu[COUT];
__device__ float g_rs[COUT];

__device__ __forceinline__ int clampi(int v, int lo, int hi) {
    return v < lo ? lo : (v > hi ? hi : v);
}

// ---------------------------------------------------------------------------
// Kernel 1: 3x3 conv (replication pad), 64->64 ch, + per-block BN partials.
// Tile: 32x32 output pixels, 4 output channels per block. 256 threads,
// each thread computes a 2x2 pixel quad x 4 channels (16 accumulators).
// cin processed in chunks of 8 through shared memory.
// Grid: (4 spatial tiles, 16 co-groups, 8 batches)
// ---------------------------------------------------------------------------
__global__ __launch_bounds__(256) void conv_kernel(
    const float* __restrict__ x, const float* __restrict__ cw,
    const float* __restrict__ cb)
{
    __shared__ float s_x[8][34][36];   // cin chunk x (32+2) x (32+2), padded stride
    __shared__ float s_w[4][8][9];
    __shared__ float s_red[2][8];

    const int tile = blockIdx.x;          // 0..3
    const int co0  = blockIdx.y * 4;      // 0..60
    const int b    = blockIdx.z;
    const int ty0  = (tile >> 1) * 32;
    const int tx0  = (tile & 1) * 32;
    const int tid  = threadIdx.x;
    const int qx   = tid & 15;
    const int qy   = tid >> 4;
    const int py   = qy * 2;              // tile-relative pixel base
    const int px   = qx * 2;

    float acc[4][2][2];
    #pragma unroll
    for (int c = 0; c < 4; c++)
        #pragma unroll
        for (int oy = 0; oy < 2; oy++)
            #pragma unroll
            for (int ox = 0; ox < 2; ox++) acc[c][oy][ox] = 0.f;

    for (int cc = 0; cc < 8; cc++) {
        // load input tile (replication-clamped)
        for (int idx = tid; idx < 8 * 34 * 34; idx += 256) {
            int ci  = idx / (34 * 34);
            int rem = idx - ci * (34 * 34);
            int yy  = rem / 34;
            int xx  = rem - yy * 34;
            int gy  = clampi(ty0 + yy - 1, 0, Hdim - 1);
            int gx  = clampi(tx0 + xx - 1, 0, Wdim - 1);
            s_x[ci][yy][xx] = x[((b * CTOT + cc * 8 + ci) * Hdim + gy) * Wdim + gx];
        }
        // load weights
        for (int idx = tid; idx < 4 * 8 * 9; idx += 256) {
            int c   = idx / 72;
            int rem = idx - c * 72;
            int ci  = rem / 9;
            int k   = rem - ci * 9;
            s_w[c][ci][k] = cw[((co0 + c) * CIN + cc * 8 + ci) * 9 + k];
        }
        __syncthreads();

        #pragma unroll
        for (int ci = 0; ci < 8; ci++) {
            float xwin[4][4];
            #pragma unroll
            for (int r = 0; r < 4; r++)
                #pragma unroll
                for (int s = 0; s < 4; s++)
                    xwin[r][s] = s_x[ci][py + r][px + s];
            #pragma unroll
            for (int c = 0; c < 4; c++) {
                #pragma unroll
                for (int ky = 0; ky < 3; ky++)
                    #pragma unroll
                    for (int kx = 0; kx < 3; kx++) {
                        float wv = s_w[c][ci][ky * 3 + kx];
                        acc[c][0][0] = fmaf(xwin[ky    ][kx    ], wv, acc[c][0][0]);
                        acc[c][0][1] = fmaf(xwin[ky    ][kx + 1], wv, acc[c][0][1]);
                        acc[c][1][0] = fmaf(xwin[ky + 1][kx    ], wv, acc[c][1][0]);
                        acc[c][1][1] = fmaf(xwin[ky + 1][kx + 1], wv, acc[c][1][1]);
                    }
            }
        }
        __syncthreads();
    }

    // bias, write raw conv output, and deterministic BN partials
    const int pidx = b * 4 + tile;
    for (int c = 0; c < 4; c++) {
        float bias = cb[co0 + c];
        float s = 0.f, s2 = 0.f;
        #pragma unroll
        for (int oy = 0; oy < 2; oy++)
            #pragma unroll
            for (int ox = 0; ox < 2; ox++) {
                float v = acc[c][oy][ox] + bias;
                g_conv[((b * COUT + co0 + c) * Hdim + ty0 + py + oy) * Wdim + tx0 + px + ox] = v;
                s += v;
                s2 += v * v;
            }
        // warp reduce
        #pragma unroll
        for (int off = 16; off > 0; off >>= 1) {
            s  += __shfl_down_sync(0xffffffffu, s,  off);
            s2 += __shfl_down_sync(0xffffffffu, s2, off);
        }
        int lane = tid & 31, wid = tid >> 5;
        if (lane == 0) { s_red[0][wid] = s; s_red[1][wid] = s2; }
        __syncthreads();
        if (tid == 0) {
            float ts = 0.f, ts2 = 0.f;
            #pragma unroll
            for (int i = 0; i < 8; i++) { ts += s_red[0][i]; ts2 += s_red[1][i]; }
            g_psum[(co0 + c) * 32 + pidx]   = ts;
            g_psumsq[(co0 + c) * 32 + pidx] = ts2;
        }
        __syncthreads();
    }
}

// ---------------------------------------------------------------------------
// Kernel 2: finalize BN stats (deterministic fixed-order reduction)
// ---------------------------------------------------------------------------
__global__ void bn_reduce()
{
    int c = threadIdx.x;
    if (c < COUT) {
        float s = 0.f, s2 = 0.f;
        #pragma unroll
        for (int i = 0; i < 32; i++) { s += g_psum[c * 32 + i]; s2 += g_psumsq[c * 32 + i]; }
        float n   = (float)(BATCH * HW);
        float mu  = s / n;
        float var = s2 / n - mu * mu;
        g_mu[c] = mu;
        g_rs[c] = rsqrtf(var + 1e-5f);
    }
}

// ---------------------------------------------------------------------------
// Kernel 3: codebook distances + channel softmax + BN-normalize + relu-attend
//           + 1x1 conv to shape query. One thread per pixel.
// ---------------------------------------------------------------------------
__global__ __launch_bounds__(128) void attend_kernel(
    const float* __restrict__ x, const float* __restrict__ sk,
    const float* __restrict__ c2w, const float* __restrict__ c2b,
    float* __restrict__ out)
{
    __shared__ float s_k[64 * 45];
    __shared__ float s_w2[64];
    __shared__ float s_mu[64];
    __shared__ float s_rs[64];
    __shared__ float s_e[128][65];   // per-thread per-code scratch (stride 65 -> no conflicts)

    const int tid = threadIdx.x;
    for (int i = tid; i < 64 * 45; i += 128) s_k[i] = sk[i];
    if (tid < 64) { s_w2[tid] = c2w[tid]; s_mu[tid] = g_mu[tid]; s_rs[tid] = g_rs[tid]; }
    __syncthreads();

    const int p  = blockIdx.x * 128 + tid;
    const int b  = p >> 12;
    const int hw = p & 4095;
    const int h  = hw >> 6;
    const int w  = hw & 63;

    // shape windows: channels 64..68, 3x3 replication-padded window
    float sw[45];
    #pragma unroll
    for (int c = 0; c < 5; c++) {
        #pragma unroll
        for (int i = 0; i < 3; i++)
            #pragma unroll
            for (int j = 0; j < 3; j++) {
                int gy = clampi(h + i - 1, 0, Hdim - 1);
                int gx = clampi(w + j - 1, 0, Wdim - 1);
                sw[c * 9 + i * 3 + j] = x[((b * CTOT + 64 + c) * Hdim + gy) * Wdim + gx];
            }
    }
    // center-subtract channels 0,1
    #pragma unroll
    for (int c = 0; c < 2; c++) {
        float ctr = sw[c * 9 + 4];
        #pragma unroll
        for (int k = 0; k < 9; k++) sw[c * 9 + k] -= ctr;
    }

    // squared distances to 64 codes
    float dmin = 3.4e38f;
    for (int co = 0; co < 64; co++) {
        float d = 0.f;
        #pragma unroll
        for (int t = 0; t < 45; t++) {
            float df = sw[t] - s_k[co * 45 + t];
            d = fmaf(df, df, d);
        }
        s_e[tid][co] = d;
        dmin = fminf(dmin, d);
    }
    // softmax over channels of -d
    float se = 0.f;
    for (int co = 0; co < 64; co++) {
        float e = __expf(dmin - s_e[tid][co]);
        s_e[tid][co] = e;
        se += e;
    }
    float inv = 1.f / se;

    float sq = c2b[0];
    for (int co = 0; co < 64; co++) {
        float wv  = s_e[tid][co] * inv;
        float cv  = (g_conv[((b * COUT + co) * Hdim + h) * Wdim + w] - s_mu[co]) * s_rs[co];
        float att = fmaxf(cv * wv, 0.f);
        out[((b * CTOT + co) * Hdim + h) * Wdim + w] = att;
        sq = fmaf(s_w2[co], att, sq);
    }
    g_sq[p] = sq;
}

// ---------------------------------------------------------------------------
// Kernel 4: window softmax of shape query (ZERO padded) + weighted window
//           statistics over channels 64..68. One thread per pixel.
// ---------------------------------------------------------------------------
__global__ __launch_bounds__(256) void agg_kernel(
    const float* __restrict__ x, float* __restrict__ out)
{
    const int p = blockIdx.x * 256 + threadIdx.x;
    if (p >= NPIX) return;
    const int b  = p >> 12;
    const int hw = p & 4095;
    const int h  = hw >> 6;
    const int w  = hw & 63;

    // q: softmax over 9 window positions of zero-padded shape query
    float qv[9];
    float qmax = -3.4e38f;
    #pragma unroll
    for (int i = 0; i < 3; i++)
        #pragma unroll
        for (int j = 0; j < 3; j++) {
            int yy = h + i - 1, xx = w + j - 1;
            float v = 0.f;
            if (yy >= 0 && yy < Hdim && xx >= 0 && xx < Wdim)
                v = g_sq[(b << 12) + (yy << 6) + xx];
            qv[i * 3 + j] = v;
            qmax = fmaxf(qmax, v);
        }
    float qs = 0.f;
    #pragma unroll
    for (int k = 0; k < 9; k++) { qv[k] = __expf(qv[k] - qmax); qs += qv[k]; }
    float qinv = 1.f / qs;
    #pragma unroll
    for (int k = 0; k < 9; k++) qv[k] *= qinv;

    // 3x3 replication-padded windows of channels 64..68
    float win[5][9];
    #pragma unroll
    for (int c = 0; c < 5; c++) {
        #pragma unroll
        for (int i = 0; i < 3; i++)
            #pragma unroll
            for (int j = 0; j < 3; j++) {
                int gy = clampi(h + i - 1, 0, Hdim - 1);
                int gx = clampi(w + j - 1, 0, Wdim - 1);
                win[c][i * 3 + j] = x[((b * CTOT + 64 + c) * Hdim + gy) * Wdim + gx];
            }
    }

    float mean0 = 0.f, mean1 = 0.f, v1_0 = 0.f, v1_1 = 0.f, c1 = 0.f;
    #pragma unroll
    for (int k = 0; k < 9; k++) {
        mean0 = fmaf(win[0][k], qv[k], mean0);
        mean1 = fmaf(win[1][k], qv[k], mean1);
        v1_0  = fmaf(win[2][k], qv[k], v1_0);
        v1_1  = fmaf(win[3][k], qv[k], v1_1);
        c1    = fmaf(win[4][k], qv[k], c1);
    }
    float v2_0 = 0.f, v2_1 = 0.f, c2 = 0.f;
    #pragma unroll
    for (int k = 0; k < 9; k++) {
        float d0 = win[0][k] - mean0;
        float d1 = win[1][k] - mean1;
        v2_0 = fmaf(d0 * d0, qv[k], v2_0);
        v2_1 = fmaf(d1 * d1, qv[k], v2_1);
        c2   = fmaf(d0 * d1, qv[k], c2);
    }

    out[((b * CTOT + 64) * Hdim + h) * Wdim + w] = mean0;
    out[((b * CTOT + 65) * Hdim + h) * Wdim + w] = mean1;
    out[((b * CTOT + 66) * Hdim + h) * Wdim + w] = v1_0 + v2_0;
    out[((b * CTOT + 67) * Hdim + h) * Wdim + w] = v1_1 + v2_1;
    out[((b * CTOT + 68) * Hdim + h) * Wdim + w] = c1 + c2;
}

// ---------------------------------------------------------------------------
extern "C" void kernel_launch(void* const* d_in, const int* in_sizes, int n_in,
                              void* d_out, int out_size)
{
    const float* x   = (const float*)d_in[0];
    const float* cw  = (const float*)d_in[1];
    const float* cb  = (const float*)d_in[2];
    const float* c2w = (const float*)d_in[3];
    const float* c2b = (const float*)d_in[4];
    const float* sk  = (const float*)d_in[5];
    float* out = (float*)d_out;

    dim3 g1(4, 16, 8);
    conv_kernel<<<g1, 256>>>(x, cw, cb);
    bn_reduce<<<1, 64>>>();
    attend_kernel<<<NPIX / 128, 128>>>(x, sk, c2w, c2b, out);
    agg_kernel<<<NPIX / 256, 256>>>(x, out);
}

// round 3
// speedup vs baseline: 1.4069x; 1.4069x over previous
#include <cuda_runtime.h>

#define BATCH 8
#define CIN   64
#define COUT  64
#define Hdim  64
#define Wdim  64
#define CTOT  69
#define HW    (Hdim*Wdim)
#define NPIX  (BATCH*HW)

// Scratch (static device globals — no allocation)
__device__ float g_conv[BATCH*COUT*HW];   // raw conv output (pre-BN)
__device__ float g_sq[NPIX];              // 1x1-conv "shape query"
__device__ float g_psum[COUT*32];         // per-(channel, block) partial sums
__device__ float g_psumsq[COUT*32];
__device__ float g_mu[COUT];
__device__ float g_rs[COUT];

__device__ __forceinline__ int clampi(int v, int lo, int hi) {
    return v < lo ? lo : (v > hi ? hi : v);
}

// ---------------------------------------------------------------------------
// Kernel 1: 3x3 conv (replication pad), 64->64 ch, + per-block BN partials.
// Tile: 32x32 output pixels, 4 output channels per block. 256 threads,
// each thread computes a 2x2 pixel quad x 4 channels (16 accumulators).
// cin processed in chunks of 8 through shared memory.
// All weights for the block preloaded once; load offsets precomputed once.
// Grid: (4 spatial tiles, 16 co-groups, 8 batches) = 512 blocks, 4/SM -> 1 wave
// ---------------------------------------------------------------------------
__global__ __launch_bounds__(256, 4) void conv_kernel(
    const float* __restrict__ x, const float* __restrict__ cw,
    const float* __restrict__ cb)
{
    __shared__ float s_x[8][34 * 35];     // cin chunk x (32+2) rows, stride 35
    __shared__ float s_w[4 * 64 * 9];     // all weights for this block's 4 couts
    __shared__ float s_red[4][2][8];

    const int tile = blockIdx.x;          // 0..3
    const int co0  = blockIdx.y * 4;      // 0..60
    const int b    = blockIdx.z;
    const int ty0  = (tile >> 1) * 32;
    const int tx0  = (tile & 1) * 32;
    const int tid  = threadIdx.x;
    const int qx   = tid & 15;
    const int qy   = tid >> 4;
    const int py   = qy * 2;              // tile-relative pixel base
    const int px   = qx * 2;

    // Preload ALL weights for this block once (flat copy: layout matches)
    for (int idx = tid; idx < 4 * 64 * 9; idx += 256)
        s_w[idx] = cw[co0 * (CIN * 9) + idx];

    // Precompute tile-fill offsets ONCE (34x34 elems, 5 slots/thread)
    int gofs[5], sofs[5];
    #pragma unroll
    for (int k = 0; k < 5; k++) {
        int idx = tid + k * 256;
        if (idx < 34 * 34) {
            int yy = idx / 34;
            int xx = idx - yy * 34;
            int gy = clampi(ty0 + yy - 1, 0, Hdim - 1);
            int gx = clampi(tx0 + xx - 1, 0, Wdim - 1);
            gofs[k] = gy * Wdim + gx;
            sofs[k] = yy * 35 + xx;
        } else {
            gofs[k] = -1;
            sofs[k] = 0;
        }
    }

    float acc[4][2][2];
    #pragma unroll
    for (int c = 0; c < 4; c++)
        #pragma unroll
        for (int oy = 0; oy < 2; oy++)
            #pragma unroll
            for (int ox = 0; ox < 2; ox++) acc[c][oy][ox] = 0.f;

    const float* xb = x + (size_t)b * CTOT * HW;

    for (int cc = 0; cc < 8; cc++) {
        __syncthreads();   // previous compute (and weight preload) done
        #pragma unroll
        for (int ci = 0; ci < 8; ci++) {
            const float* xc = xb + (cc * 8 + ci) * HW;
            #pragma unroll
            for (int k = 0; k < 5; k++)
                if (gofs[k] >= 0) s_x[ci][sofs[k]] = __ldg(xc + gofs[k]);
        }
        __syncthreads();

        #pragma unroll
        for (int ci = 0; ci < 8; ci++) {
            float xwin[4][4];
            #pragma unroll
            for (int r = 0; r < 4; r++)
                #pragma unroll
                for (int s = 0; s < 4; s++)
                    xwin[r][s] = s_x[ci][(py + r) * 35 + px + s];
            const float* wv_base = &s_w[(cc * 8 + ci) * 9];
            #pragma unroll
            for (int c = 0; c < 4; c++) {
                #pragma unroll
                for (int ky = 0; ky < 3; ky++)
                    #pragma unroll
                    for (int kx = 0; kx < 3; kx++) {
                        float wv = wv_base[c * 64 * 9 + ky * 3 + kx];
                        acc[c][0][0] = fmaf(xwin[ky    ][kx    ], wv, acc[c][0][0]);
                        acc[c][0][1] = fmaf(xwin[ky    ][kx + 1], wv, acc[c][0][1]);
                        acc[c][1][0] = fmaf(xwin[ky + 1][kx    ], wv, acc[c][1][0]);
                        acc[c][1][1] = fmaf(xwin[ky + 1][kx + 1], wv, acc[c][1][1]);
                    }
            }
        }
    }

    // bias, write raw conv output, and deterministic BN partials (1 sync total)
    const int pidx = b * 4 + tile;
    const int lane = tid & 31, wid = tid >> 5;
    #pragma unroll
    for (int c = 0; c < 4; c++) {
        float bias = cb[co0 + c];
        float s = 0.f, s2 = 0.f;
        #pragma unroll
        for (int oy = 0; oy < 2; oy++)
            #pragma unroll
            for (int ox = 0; ox < 2; ox++) {
                float v = acc[c][oy][ox] + bias;
                g_conv[((b * COUT + co0 + c) * Hdim + ty0 + py + oy) * Wdim + tx0 + px + ox] = v;
                s += v;
                s2 += v * v;
            }
        #pragma unroll
        for (int off = 16; off > 0; off >>= 1) {
            s  += __shfl_down_sync(0xffffffffu, s,  off);
            s2 += __shfl_down_sync(0xffffffffu, s2, off);
        }
        if (lane == 0) { s_red[c][0][wid] = s; s_red[c][1][wid] = s2; }
    }
    __syncthreads();
    if (tid < 4) {
        float ts = 0.f, ts2 = 0.f;
        #pragma unroll
        for (int i = 0; i < 8; i++) { ts += s_red[tid][0][i]; ts2 += s_red[tid][1][i]; }
        g_psum[(co0 + tid) * 32 + pidx]   = ts;
        g_psumsq[(co0 + tid) * 32 + pidx] = ts2;
    }
}

// ---------------------------------------------------------------------------
// Kernel 2: finalize BN stats (deterministic fixed-order reduction)
// ---------------------------------------------------------------------------
__global__ void bn_reduce()
{
    int c = threadIdx.x;
    if (c < COUT) {
        float s = 0.f, s2 = 0.f;
        #pragma unroll
        for (int i = 0; i < 32; i++) { s += g_psum[c * 32 + i]; s2 += g_psumsq[c * 32 + i]; }
        float n   = (float)(BATCH * HW);
        float mu  = s / n;
        float var = s2 / n - mu * mu;
        g_mu[c] = mu;
        g_rs[c] = rsqrtf(var + 1e-5f);
    }
}

// ---------------------------------------------------------------------------
// Kernel 3: codebook distances + channel softmax + BN-normalize + relu-attend
//           + 1x1 conv to shape query. One thread per pixel.
// ---------------------------------------------------------------------------
__global__ __launch_bounds__(128) void attend_kernel(
    const float* __restrict__ x, const float* __restrict__ sk,
    const float* __restrict__ c2w, const float* __restrict__ c2b,
    float* __restrict__ out)
{
    __shared__ float s_k[64 * 45];
    __shared__ float s_w2[64];
    __shared__ float s_mu[64];
    __shared__ float s_rs[64];
    __shared__ float s_e[128][65];   // per-thread per-code scratch (stride 65 -> no conflicts)

    const int tid = threadIdx.x;
    for (int i = tid; i < 64 * 45; i += 128) s_k[i] = sk[i];
    if (tid < 64) { s_w2[tid] = c2w[tid]; s_mu[tid] = g_mu[tid]; s_rs[tid] = g_rs[tid]; }
    __syncthreads();

    const int p  = blockIdx.x * 128 + tid;
    const int b  = p >> 12;
    const int hw = p & 4095;
    const int h  = hw >> 6;
    const int w  = hw & 63;

    // shape windows: channels 64..68, 3x3 replication-padded window
    float sw[45];
    #pragma unroll
    for (int c = 0; c < 5; c++) {
        #pragma unroll
        for (int i = 0; i < 3; i++)
            #pragma unroll
            for (int j = 0; j < 3; j++) {
                int gy = clampi(h + i - 1, 0, Hdim - 1);
                int gx = clampi(w + j - 1, 0, Wdim - 1);
                sw[c * 9 + i * 3 + j] = x[((b * CTOT + 64 + c) * Hdim + gy) * Wdim + gx];
            }
    }
    // center-subtract channels 0,1
    #pragma unroll
    for (int c = 0; c < 2; c++) {
        float ctr = sw[c * 9 + 4];
        #pragma unroll
        for (int k = 0; k < 9; k++) sw[c * 9 + k] -= ctr;
    }

    // squared distances to 64 codes
    float dmin = 3.4e38f;
    for (int co = 0; co < 64; co++) {
        float d = 0.f;
        #pragma unroll
        for (int t = 0; t < 45; t++) {
            float df = sw[t] - s_k[co * 45 + t];
            d = fmaf(df, df, d);
        }
        s_e[tid][co] = d;
        dmin = fminf(dmin, d);
    }
    // softmax over channels of -d
    float se = 0.f;
    for (int co = 0; co < 64; co++) {
        float e = __expf(dmin - s_e[tid][co]);
        s_e[tid][co] = e;
        se += e;
    }
    float inv = 1.f / se;

    float sq = c2b[0];
    for (int co = 0; co < 64; co++) {
        float wv  = s_e[tid][co] * inv;
        float cv  = (g_conv[((b * COUT + co) * Hdim + h) * Wdim + w] - s_mu[co]) * s_rs[co];
        float att = fmaxf(cv * wv, 0.f);
        out[((b * CTOT + co) * Hdim + h) * Wdim + w] = att;
        sq = fmaf(s_w2[co], att, sq);
    }
    g_sq[p] = sq;
}

// ---------------------------------------------------------------------------
// Kernel 4: window softmax of shape query (ZERO padded) + weighted window
//           statistics over channels 64..68. One thread per pixel.
// ---------------------------------------------------------------------------
__global__ __launch_bounds__(256) void agg_kernel(
    const float* __restrict__ x, float* __restrict__ out)
{
    const int p = blockIdx.x * 256 + threadIdx.x;
    if (p >= NPIX) return;
    const int b  = p >> 12;
    const int hw = p & 4095;
    const int h  = hw >> 6;
    const int w  = hw & 63;

    // q: softmax over 9 window positions of zero-padded shape query
    float qv[9];
    float qmax = -3.4e38f;
    #pragma unroll
    for (int i = 0; i < 3; i++)
        #pragma unroll
        for (int j = 0; j < 3; j++) {
            int yy = h + i - 1, xx = w + j - 1;
            float v = 0.f;
            if (yy >= 0 && yy < Hdim && xx >= 0 && xx < Wdim)
                v = g_sq[(b << 12) + (yy << 6) + xx];
            qv[i * 3 + j] = v;
            qmax = fmaxf(qmax, v);
        }
    float qs = 0.f;
    #pragma unroll
    for (int k = 0; k < 9; k++) { qv[k] = __expf(qv[k] - qmax); qs += qv[k]; }
    float qinv = 1.f / qs;
    #pragma unroll
    for (int k = 0; k < 9; k++) qv[k] *= qinv;

    // 3x3 replication-padded windows of channels 64..68
    float win[5][9];
    #pragma unroll
    for (int c = 0; c < 5; c++) {
        #pragma unroll
        for (int i = 0; i < 3; i++)
            #pragma unroll
            for (int j = 0; j < 3; j++) {
                int gy = clampi(h + i - 1, 0, Hdim - 1);
                int gx = clampi(w + j - 1, 0, Wdim - 1);
                win[c][i * 3 + j] = x[((b * CTOT + 64 + c) * Hdim + gy) * Wdim + gx];
            }
    }

    float mean0 = 0.f, mean1 = 0.f, v1_0 = 0.f, v1_1 = 0.f, c1 = 0.f;
    #pragma unroll
    for (int k = 0; k < 9; k++) {
        mean0 = fmaf(win[0][k], qv[k], mean0);
        mean1 = fmaf(win[1][k], qv[k], mean1);
        v1_0  = fmaf(win[2][k], qv[k], v1_0);
        v1_1  = fmaf(win[3][k], qv[k], v1_1);
        c1    = fmaf(win[4][k], qv[k], c1);
    }
    float v2_0 = 0.f, v2_1 = 0.f, c2 = 0.f;
    #pragma unroll
    for (int k = 0; k < 9; k++) {
        float d0 = win[0][k] - mean0;
        float d1 = win[1][k] - mean1;
        v2_0 = fmaf(d0 * d0, qv[k], v2_0);
        v2_1 = fmaf(d1 * d1, qv[k], v2_1);
        c2   = fmaf(d0 * d1, qv[k], c2);
    }

    out[((b * CTOT + 64) * Hdim + h) * Wdim + w] = mean0;
    out[((b * CTOT + 65) * Hdim + h) * Wdim + w] = mean1;
    out[((b * CTOT + 66) * Hdim + h) * Wdim + w] = v1_0 + v2_0;
    out[((b * CTOT + 67) * Hdim + h) * Wdim + w] = v1_1 + v2_1;
    out[((b * CTOT + 68) * Hdim + h) * Wdim + w] = c1 + c2;
}

// ---------------------------------------------------------------------------
extern "C" void kernel_launch(void* const* d_in, const int* in_sizes, int n_in,
                              void* d_out, int out_size)
{
    const float* x   = (const float*)d_in[0];
    const float* cw  = (const float*)d_in[1];
    const float* cb  = (const float*)d_in[2];
    const float* c2w = (const float*)d_in[3];
    const float* c2b = (const float*)d_in[4];
    const float* sk  = (const float*)d_in[5];
    float* out = (float*)d_out;

    dim3 g1(4, 16, 8);
    conv_kernel<<<g1, 256>>>(x, cw, cb);
    bn_reduce<<<1, 64>>>();
    attend_kernel<<<NPIX / 128, 128>>>(x, sk, c2w, c2b, out);
    agg_kernel<<<NPIX / 256, 256>>>(x, out);
}

// round 5
// speedup vs baseline: 2.8690x; 2.0392x over previous
#include <cuda_runtime.h>
#include <cstdint>

#define BATCH 8
#define CIN   64
#define COUT  64
#define Hdim  64
#define Wdim  64
#define CTOT  69
#define HW    (Hdim*Wdim)
#define NPIX  (BATCH*HW)

// Scratch (static device globals — no allocation)
__device__ float g_conv[BATCH*COUT*HW];   // raw conv output (pre-BN)
__device__ float g_sq[NPIX];              // 1x1-conv "shape query"
__device__ float g_psum[COUT*8];          // per-(co,b) partial sums
__device__ float g_psumsq[COUT*8];
__device__ float g_mu[COUT];
__device__ float g_rs[COUT];
__device__ __align__(16) float g_wt[9*4096];  // weights in B-fragment order

__device__ __forceinline__ int clampi(int v, int lo, int hi) {
    return v < lo ? lo : (v > hi ? hi : v);
}
__device__ __forceinline__ float f2tf32f(float f) {
    uint32_t r; asm("cvt.rna.tf32.f32 %0, %1;" : "=r"(r) : "f"(f));
    return __uint_as_float(r);
}

// m16n8k8 tf32 mma: D += A*B (D==C, fp32 accum). a: 4 regs, b: 2 regs.
__device__ __forceinline__ void mma8(float* d, const uint32_t* a, uint32_t b0, uint32_t b1) {
    asm volatile(
        "mma.sync.aligned.m16n8k8.row.col.f32.tf32.tf32.f32 "
        "{%0,%1,%2,%3}, {%4,%5,%6,%7}, {%8,%9}, {%0,%1,%2,%3};\n"
        : "+f"(d[0]), "+f"(d[1]), "+f"(d[2]), "+f"(d[3])
        : "r"(a[0]), "r"(a[1]), "r"(a[2]), "r"(a[3]), "r"(b0), "r"(b1));
}

// ---------------------------------------------------------------------------
// Kernel 0: transform conv weights into B-fragment order (tf32-rounded).
// wt[(((kidx*8+kk)*8+nt)*32+lane)*2+r] = cw[co][ci][ky][kx]
//   co = nt*8 + (lane>>2), ci = kk*8 + (lane&3) + 4*r, kidx = ky*3+kx
// ---------------------------------------------------------------------------
__global__ __launch_bounds__(256) void wt_transform(const float* __restrict__ cw)
{
    int idx = blockIdx.x * 256 + threadIdx.x;
    if (idx >= 9 * 4096) return;
    int r    = idx & 1;
    int lane = (idx >> 1) & 31;
    int nt   = (idx >> 6) & 7;
    int kk   = (idx >> 9) & 7;
    int kidx = idx >> 12;
    int gid = lane >> 2, tig = lane & 3;
    int co = nt * 8 + gid;
    int ci = kk * 8 + tig + 4 * r;
    g_wt[idx] = f2tf32f(cw[(co * CIN + ci) * 9 + kidx]);
}

// ---------------------------------------------------------------------------
// Kernel 1: 3x3 conv (replication pad) via mma.sync tf32 implicit GEMM.
// Block: 128 pixels (2 output rows) x 64 couts, 256 threads / 8 warps.
// Warp tile 32x32: 2 m16 tiles x 4 n8 tiles. K = 9 x (8 k8-steps over ci).
// A fragments read directly from a stride-264 x-slab (conflict-free banks);
// B chunks streamed from fragment-ordered g_wt with register prefetch.
// Grid: 256 blocks (b = blk>>5, h0 = (blk&31)*2).
// ---------------------------------------------------------------------------
#define SLAB_STRIDE 264
#define SLAB_FLOATS (64*SLAB_STRIDE)          // 16896
#define BBUF_FLOATS 4096
#define DYN_SMEM ((SLAB_FLOATS + BBUF_FLOATS) * 4)   // 83968 B

__global__ __launch_bounds__(256, 2) void conv_mma_kernel(
    const float* __restrict__ x, const float* __restrict__ cb)
{
    extern __shared__ float smem[];
    float* slab = smem;                 // [64 ci][256 rc] stride 264
    float* bbuf = smem + SLAB_FLOATS;   // B fragments for current (ky,kx)

    const int tid  = threadIdx.x;
    const int lane = tid & 31;
    const int w    = tid >> 5;
    const int gid  = lane >> 2;
    const int tig  = lane & 3;
    const int wm   = (w & 3) * 32;      // pixel offset
    const int wn   = (w >> 2) * 32;     // cout offset
    const int blk  = blockIdx.x;
    const int b    = blk >> 5;
    const int h0   = (blk & 31) * 2;

    // ---- slab fill: x[b][ci][h0-1..h0+2 clamped][:], tf32-rounded ----
    const float* xb = x + (size_t)b * CTOT * HW;
    #pragma unroll
    for (int i = 0; i < 64; i++) {
        int idx = i * 256 + tid;
        int ci  = idx >> 8;
        int rc  = idx & 255;
        int rr  = rc >> 6;
        int col = rc & 63;
        int row = clampi(h0 - 1 + rr, 0, Hdim - 1);
        slab[ci * SLAB_STRIDE + rc] = f2tf32f(__ldg(xb + (ci * Hdim + row) * Wdim + col));
    }

    // ---- prefetch B chunk kidx=0 ----
    const float4* wt4 = (const float4*)g_wt;
    float4 pf[4];
    #pragma unroll
    for (int j = 0; j < 4; j++) pf[j] = __ldg(wt4 + j * 256 + tid);

    float acc[2][4][4];
    #pragma unroll
    for (int tm = 0; tm < 2; tm++)
        #pragma unroll
        for (int nt = 0; nt < 4; nt++)
            #pragma unroll
            for (int c = 0; c < 4; c++) acc[tm][nt][c] = 0.f;

    __syncthreads();   // slab ready

    // per-tm fixed pixel geometry
    int dy[2], col_lo[2], col_hi[2];
    #pragma unroll
    for (int tm = 0; tm < 2; tm++) {
        int pix = wm + tm * 16 + gid;
        dy[tm] = pix >> 6;
        col_lo[tm] = pix & 63;
        col_hi[tm] = col_lo[tm] + 8;
    }

    float4* bb4 = (float4*)bbuf;

    for (int kidx = 0; kidx < 9; kidx++) {
        const int ky = kidx / 3, kx = kidx % 3;
        if (kidx > 0) __syncthreads();           // prior bbuf reads done
        #pragma unroll
        for (int j = 0; j < 4; j++) bb4[j * 256 + tid] = pf[j];
        __syncthreads();
        if (kidx < 8) {
            #pragma unroll
            for (int j = 0; j < 4; j++)
                pf[j] = __ldg(wt4 + (kidx + 1) * 1024 + j * 256 + tid);
        }

        int off_lo[2], off_hi[2];
        #pragma unroll
        for (int tm = 0; tm < 2; tm++) {
            int rowoff = (dy[tm] + ky) * 64;
            off_lo[tm] = rowoff + clampi(col_lo[tm] + kx - 1, 0, 63);
            off_hi[tm] = rowoff + clampi(col_hi[tm] + kx - 1, 0, 63);
        }

        #pragma unroll
        for (int kk = 0; kk < 8; kk++) {
            const int cib  = (kk * 8 + tig) * SLAB_STRIDE;
            const int cib4 = cib + 4 * SLAB_STRIDE;
            uint32_t a[2][4];
            #pragma unroll
            for (int tm = 0; tm < 2; tm++) {
                a[tm][0] = __float_as_uint(slab[cib  + off_lo[tm]]);
                a[tm][1] = __float_as_uint(slab[cib  + off_hi[tm]]);
                a[tm][2] = __float_as_uint(slab[cib4 + off_lo[tm]]);
                a[tm][3] = __float_as_uint(slab[cib4 + off_hi[tm]]);
            }
            #pragma unroll
            for (int nt = 0; nt < 4; nt++) {
                int ntg = (wn >> 3) + nt;
                float2 bf = *(const float2*)&bbuf[((kk * 8 + ntg) * 32 + lane) * 2];
                uint32_t b0 = __float_as_uint(bf.x);
                uint32_t b1 = __float_as_uint(bf.y);
                mma8(acc[0][nt], a[0], b0, b1);
                mma8(acc[1][nt], a[1], b0, b1);
            }
        }
    }

    // ---- epilogue: +bias, write g_conv ----
    #pragma unroll
    for (int tm = 0; tm < 2; tm++) {
        float* grow = g_conv + ((size_t)b * COUT * Hdim + (h0 + dy[tm])) * Wdim;
        #pragma unroll
        for (int nt = 0; nt < 4; nt++) {
            int co0 = wn + nt * 8 + 2 * tig;
            float b0 = __ldg(cb + co0), b1 = __ldg(cb + co0 + 1);
            grow[(size_t)co0       * HW + col_lo[tm]] = acc[tm][nt][0] + b0;
            grow[(size_t)(co0 + 1) * HW + col_lo[tm]] = acc[tm][nt][1] + b1;
            grow[(size_t)co0       * HW + col_hi[tm]] = acc[tm][nt][2] + b0;
            grow[(size_t)(co0 + 1) * HW + col_hi[tm]] = acc[tm][nt][3] + b1;
        }
    }
}

// ---------------------------------------------------------------------------
// Kernel 2a: BN partial sums per (co, b), deterministic fixed-order tree
// ---------------------------------------------------------------------------
__global__ __launch_bounds__(128) void bn_partial()
{
    __shared__ float ss[128], ss2[128];
    const int co = blockIdx.x & 63;
    const int b  = blockIdx.x >> 6;
    const int t  = threadIdx.x;
    const float* p = g_conv + ((size_t)(b * COUT + co)) * HW;
    float s = 0.f, s2 = 0.f;
    #pragma unroll
    for (int j = 0; j < 32; j++) {
        float v = p[t + j * 128];
        s += v; s2 += v * v;
    }
    ss[t] = s; ss2[t] = s2;
    __syncthreads();
    for (int o = 64; o > 0; o >>= 1) {
        if (t < o) { ss[t] += ss[t + o]; ss2[t] += ss2[t + o]; }
        __syncthreads();
    }
    if (t == 0) { g_psum[co * 8 + b] = ss[0]; g_psumsq[co * 8 + b] = ss2[0]; }
}

// ---------------------------------------------------------------------------
// Kernel 2b: finalize BN stats
// ---------------------------------------------------------------------------
__global__ void bn_reduce()
{
    int c = threadIdx.x;
    if (c < COUT) {
        float s = 0.f, s2 = 0.f;
        #pragma unroll
        for (int i = 0; i < 8; i++) { s += g_psum[c * 8 + i]; s2 += g_psumsq[c * 8 + i]; }
        float n   = (float)(BATCH * HW);
        float mu  = s / n;
        float var = s2 / n - mu * mu;
        g_mu[c] = mu;
        g_rs[c] = rsqrtf(var + 1e-5f);
    }
}

// ---------------------------------------------------------------------------
// Kernel 3: codebook distances + channel softmax + BN-normalize + relu-attend
//           + 1x1 conv to shape query. One thread per pixel.
// ---------------------------------------------------------------------------
__global__ __launch_bounds__(128) void attend_kernel(
    const float* __restrict__ x, const float* __restrict__ sk,
    const float* __restrict__ c2w, const float* __restrict__ c2b,
    float* __restrict__ out)
{
    __shared__ float s_k[64 * 45];
    __shared__ float s_w2[64];
    __shared__ float s_mu[64];
    __shared__ float s_rs[64];
    __shared__ float s_e[128][65];

    const int tid = threadIdx.x;
    for (int i = tid; i < 64 * 45; i += 128) s_k[i] = sk[i];
    if (tid < 64) { s_w2[tid] = c2w[tid]; s_mu[tid] = g_mu[tid]; s_rs[tid] = g_rs[tid]; }
    __syncthreads();

    const int p  = blockIdx.x * 128 + tid;
    const int b  = p >> 12;
    const int hw = p & 4095;
    const int h  = hw >> 6;
    const int w  = hw & 63;

    float sw[45];
    #pragma unroll
    for (int c = 0; c < 5; c++) {
        #pragma unroll
        for (int i = 0; i < 3; i++)
            #pragma unroll
            for (int j = 0; j < 3; j++) {
                int gy = clampi(h + i - 1, 0, Hdim - 1);
                int gx = clampi(w + j - 1, 0, Wdim - 1);
                sw[c * 9 + i * 3 + j] = x[((b * CTOT + 64 + c) * Hdim + gy) * Wdim + gx];
            }
    }
    #pragma unroll
    for (int c = 0; c < 2; c++) {
        float ctr = sw[c * 9 + 4];
        #pragma unroll
        for (int k = 0; k < 9; k++) sw[c * 9 + k] -= ctr;
    }

    float dmin = 3.4e38f;
    for (int co = 0; co < 64; co++) {
        float d = 0.f;
        #pragma unroll
        for (int t2 = 0; t2 < 45; t2++) {
            float df = sw[t2] - s_k[co * 45 + t2];
            d = fmaf(df, df, d);
        }
        s_e[tid][co] = d;
        dmin = fminf(dmin, d);
    }
    float se = 0.f;
    for (int co = 0; co < 64; co++) {
        float e = __expf(dmin - s_e[tid][co]);
        s_e[tid][co] = e;
        se += e;
    }
    float inv = 1.f / se;

    float sq = c2b[0];
    for (int co = 0; co < 64; co++) {
        float wv  = s_e[tid][co] * inv;
        float cv  = (g_conv[((b * COUT + co) * Hdim + h) * Wdim + w] - s_mu[co]) * s_rs[co];
        float att = fmaxf(cv * wv, 0.f);
        out[((b * CTOT + co) * Hdim + h) * Wdim + w] = att;
        sq = fmaf(s_w2[co], att, sq);
    }
    g_sq[p] = sq;
}

// ---------------------------------------------------------------------------
// Kernel 4: window softmax of shape query (zero-padded) + weighted stats
// ---------------------------------------------------------------------------
__global__ __launch_bounds__(256) void agg_kernel(
    const float* __restrict__ x, float* __restrict__ out)
{
    const int p = blockIdx.x * 256 + threadIdx.x;
    if (p >= NPIX) return;
    const int b  = p >> 12;
    const int hw = p & 4095;
    const int h  = hw >> 6;
    const int w  = hw & 63;

    float qv[9];
    float qmax = -3.4e38f;
    #pragma unroll
    for (int i = 0; i < 3; i++)
        #pragma unroll
        for (int j = 0; j < 3; j++) {
            int yy = h + i - 1, xx = w + j - 1;
            float v = 0.f;
            if (yy >= 0 && yy < Hdim && xx >= 0 && xx < Wdim)
                v = g_sq[(b << 12) + (yy << 6) + xx];
            qv[i * 3 + j] = v;
            qmax = fmaxf(qmax, v);
        }
    float qs = 0.f;
    #pragma unroll
    for (int k = 0; k < 9; k++) { qv[k] = __expf(qv[k] - qmax); qs += qv[k]; }
    float qinv = 1.f / qs;
    #pragma unroll
    for (int k = 0; k < 9; k++) qv[k] *= qinv;

    float win[5][9];
    #pragma unroll
    for (int c = 0; c < 5; c++) {
        #pragma unroll
        for (int i = 0; i < 3; i++)
            #pragma unroll
            for (int j = 0; j < 3; j++) {
                int gy = clampi(h + i - 1, 0, Hdim - 1);
                int gx = clampi(w + j - 1, 0, Wdim - 1);
                win[c][i * 3 + j] = x[((b * CTOT + 64 + c) * Hdim + gy) * Wdim + gx];
            }
    }

    float mean0 = 0.f, mean1 = 0.f, v1_0 = 0.f, v1_1 = 0.f, c1 = 0.f;
    #pragma unroll
    for (int k = 0; k < 9; k++) {
        mean0 = fmaf(win[0][k], qv[k], mean0);
        mean1 = fmaf(win[1][k], qv[k], mean1);
        v1_0  = fmaf(win[2][k], qv[k], v1_0);
        v1_1  = fmaf(win[3][k], qv[k], v1_1);
        c1    = fmaf(win[4][k], qv[k], c1);
    }
    float v2_0 = 0.f, v2_1 = 0.f, c2 = 0.f;
    #pragma unroll
    for (int k = 0; k < 9; k++) {
        float d0 = win[0][k] - mean0;
        float d1 = win[1][k] - mean1;
        v2_0 = fmaf(d0 * d0, qv[k], v2_0);
        v2_1 = fmaf(d1 * d1, qv[k], v2_1);
        c2   = fmaf(d0 * d1, qv[k], c2);
    }

    out[((b * CTOT + 64) * Hdim + h) * Wdim + w] = mean0;
    out[((b * CTOT + 65) * Hdim + h) * Wdim + w] = mean1;
    out[((b * CTOT + 66) * Hdim + h) * Wdim + w] = v1_0 + v2_0;
    out[((b * CTOT + 67) * Hdim + h) * Wdim + w] = v1_1 + v2_1;
    out[((b * CTOT + 68) * Hdim + h) * Wdim + w] = c1 + c2;
}

// ---------------------------------------------------------------------------
extern "C" void kernel_launch(void* const* d_in, const int* in_sizes, int n_in,
                              void* d_out, int out_size)
{
    const float* x   = (const float*)d_in[0];
    const float* cw  = (const float*)d_in[1];
    const float* cb  = (const float*)d_in[2];
    const float* c2w = (const float*)d_in[3];
    const float* c2b = (const float*)d_in[4];
    const float* sk  = (const float*)d_in[5];
    float* out = (float*)d_out;

    static bool attr_set = false;
    if (!attr_set) {
        cudaFuncSetAttribute(conv_mma_kernel,
                             cudaFuncAttributeMaxDynamicSharedMemorySize, DYN_SMEM);
        attr_set = true;
    }

    wt_transform<<<144, 256>>>(cw);
    conv_mma_kernel<<<256, 256, DYN_SMEM>>>(x, cb);
    bn_partial<<<512, 128>>>();
    bn_reduce<<<1, 64>>>();
    attend_kernel<<<NPIX / 128, 128>>>(x, sk, c2w, c2b, out);
    agg_kernel<<<NPIX / 256, 256>>>(x, out);
}